// round 5
// baseline (speedup 1.0000x reference)
#include <cuda_runtime.h>
#include <cstdint>

// ---------------------------------------------------------------------------
// DifferentiableBiquadChain: 16 cascaded SVF biquads, per-frame coefficients.
//
// Block = (batch-pair, frame): 256 threads x 8 samples x 2 batches (f32x2
// packed — batch0 in lo lane, batch1 in hi lane). Per filter: zero-state sim
// -> warp affine scan (constant-A per frame, powers by repeated squaring) ->
// cross-warp combine in smem -> cross-frame state via wavefront publish/spin
// (relaxed 64-bit atomics, NaN sentinel) -> exact re-simulation with
// reference arithmetic. Audio stays in registers across all 16 stages.
// ---------------------------------------------------------------------------

#define NB      16
#define FRAME   2048
#define NFR     24
#define BATCH   32
#define NPAIR   16
#define TPB     256
#define SPT     8
#define NW      8
#define SVAL    0xFFFFFFFFFFFFFFFFull

typedef unsigned long long ull;

__device__ ull g_state[BATCH * NFR * NB];

__global__ void init_state_kernel() {
    int i = blockIdx.x * blockDim.x + threadIdx.x;
    if (i < BATCH * NFR * NB) g_state[i] = SVAL;
}

// ---- packed f32x2 helpers -------------------------------------------------
__device__ __forceinline__ ull fma2(ull a, ull b, ull c) {
    ull d; asm("fma.rn.f32x2 %0,%1,%2,%3;" : "=l"(d) : "l"(a), "l"(b), "l"(c)); return d;
}
__device__ __forceinline__ ull mul2(ull a, ull b) {
    ull d; asm("mul.rn.f32x2 %0,%1,%2;" : "=l"(d) : "l"(a), "l"(b)); return d;
}
__device__ __forceinline__ ull add2(ull a, ull b) {
    ull d; asm("add.rn.f32x2 %0,%1,%2;" : "=l"(d) : "l"(a), "l"(b)); return d;
}
__device__ __forceinline__ ull neg2(ull a) { return a ^ 0x8000000080000000ull; }
__device__ __forceinline__ ull pack2(float lo, float hi) {
    ull r; asm("mov.b64 %0,{%1,%2};" : "=l"(r) : "f"(lo), "f"(hi)); return r;
}
__device__ __forceinline__ float lo2(ull a) {
    float f; asm("{ .reg .f32 h; mov.b64 {%0,h}, %1; }" : "=f"(f) : "l"(a)); return f;
}
__device__ __forceinline__ float hi2(ull a) {
    float f; asm("{ .reg .f32 l; mov.b64 {l,%0}, %1; }" : "=f"(f) : "l"(a)); return f;
}

#define ONE2    0x3F8000003F800000ull   // { 1, 1 }
#define NEG1_2  0xBF800000BF800000ull   // {-1,-1 }
#define TWO2    0x4000000040000000ull   // { 2, 2 }
#define NEGTWO2 0xC0000000C0000000ull   // {-2,-2 }

struct M2p { ull a, b, c, d; };

__device__ __forceinline__ M2p msq(M2p m) {
    M2p r;
    ull apd = add2(m.a, m.d);
    ull bc  = mul2(m.b, m.c);
    r.a = fma2(m.a, m.a, bc);
    r.b = mul2(m.b, apd);
    r.c = mul2(m.c, apd);
    r.d = fma2(m.d, m.d, bc);
    return r;
}
__device__ __forceinline__ M2p mmul(M2p p, M2p q) {
    M2p r;
    r.a = fma2(p.a, q.a, mul2(p.b, q.c));
    r.b = fma2(p.a, q.b, mul2(p.b, q.d));
    r.c = fma2(p.c, q.a, mul2(p.d, q.c));
    r.d = fma2(p.c, q.b, mul2(p.d, q.d));
    return r;
}

__device__ __forceinline__ ull ld_relaxed_u64(const ull* p) {
    ull v;
    asm volatile("ld.relaxed.gpu.global.u64 %0, [%1];" : "=l"(v) : "l"(p) : "memory");
    return v;
}
__device__ __forceinline__ void st_relaxed_u64(ull* p, ull v) {
    asm volatile("st.relaxed.gpu.global.u64 [%0], %1;" : : "l"(p), "l"(v) : "memory");
}

__global__ __launch_bounds__(TPB, 3)
void eq_kernel(const float* __restrict__ audio,
               const float* __restrict__ params,
               float* __restrict__ out)
{
    const int blk  = blockIdx.x;
    const int f    = blk >> 4;    // frame (f-major: predecessors have lower blockIdx)
    const int pr   = blk & 15;    // batch pair
    const int b0   = pr * 2;
    const int t    = threadIdx.x;
    const int lane = t & 31;
    const int w    = t >> 5;      // warp 0..7

    __shared__ ull cf[NB][6];        // packed a1 a2 a3 m0 m1 m2 (lo=b0, hi=b1)
    __shared__ ull shT[2][NW][2];    // double-buffered warp totals
    __shared__ ull sh_sin[2];        // frame incoming state (packed)
    __shared__ ull sh_gain[2];       // packed in_g, out_g

    // ---------------- coefficients (threads 0..35) ----------------
    if (t < 32) {
        const int bi = t >> 4;       // which batch of the pair
        const int i  = t & 15;       // filter index
        const float* pb = params + (size_t)((b0 + bi) * 50) * NFR + f;
        float fn = pb[(i * 3 + 0) * NFR];
        float gn = pb[(i * 3 + 1) * NFR];
        float qn = pb[(i * 3 + 2) * NFR];

        float Q = expf(fmaf(qn, 3.4657359f, -0.6931472f));   // 0.5..16 log-spaced
        Q = fminf(fmaxf(Q, 0.1f), 100.0f);

        float gain = fmaf(gn, 48.0f, -24.0f);
        float A  = exp10f(gain * 0.025f);
        float sA = sqrtf(A);

        float lnlo, lnhi;
        if      (i == 0)            { lnlo = 2.9957323f; lnhi = 6.2146081f; } // HPF 20..500
        else if (i == 15)           { lnlo = 8.5171932f; lnhi = 9.9034876f; } // LPF 5k..20k
        else if (i == 1 || i == 14) { lnlo = 3.9120230f; lnhi = 9.6803184f; } // shelf 50..16k
        else                        { lnlo = 4.6051702f; lnhi = 9.6158055f; } // peak 100..15k
        float fc = expf(fmaf(fn, (lnhi - lnlo), lnlo));
        float g  = tanf(fc * 3.27249235e-5f);                 // tan(pi*fc/96000)
        g = fminf(fmaxf(g, 1e-6f), 100.0f);

        float a1, a2, a3, m0, m1, m2;
        if (i == 0) {            // highpass
            float k = 1.0f / Q;
            a1 = 1.0f / (1.0f + g * (g + k)); a2 = g * a1; a3 = g * a2;
            m0 = 1.0f; m1 = -k; m2 = -1.0f;
        } else if (i == 15) {    // lowpass
            float k = 1.0f / Q;
            a1 = 1.0f / (1.0f + g * (g + k)); a2 = g * a1; a3 = g * a2;
            m0 = 0.0f; m1 = 0.0f; m2 = 1.0f;
        } else if (i == 1) {     // lowshelf
            float k = 1.0f / Q;
            float gs = (gain >= 0.0f) ? (g / sA) : (g * sA);
            a1 = 1.0f / (1.0f + gs * (gs + k)); a2 = gs * a1; a3 = gs * a2;
            m0 = 1.0f; m1 = k * (A - 1.0f); m2 = A * A - 1.0f;
        } else if (i == 14) {    // highshelf
            float k = 1.0f / Q;
            float gs = (gain >= 0.0f) ? (g * sA) : (g / sA);
            a1 = 1.0f / (1.0f + gs * (gs + k)); a2 = gs * a1; a3 = gs * a2;
            m0 = A * A; m1 = k * (1.0f - A) * A; m2 = 1.0f - A * A;
        } else {                 // peak
            float k = (gain >= 0.0f) ? (1.0f / (Q * A)) : (A / Q);
            a1 = 1.0f / (1.0f + g * (g + k)); a2 = g * a1; a3 = g * a2;
            m0 = 1.0f; m1 = k * (A * A - 1.0f); m2 = 0.0f;
        }
        ((float*)&cf[i][0])[bi] = a1;
        ((float*)&cf[i][1])[bi] = a2;
        ((float*)&cf[i][2])[bi] = a3;
        ((float*)&cf[i][3])[bi] = m0;
        ((float*)&cf[i][4])[bi] = m1;
        ((float*)&cf[i][5])[bi] = m2;
    } else if (t < 36) {
        const int idx   = t - 32;
        const int which = idx >> 1;  // 0: in_g, 1: out_g
        const int bi    = idx & 1;
        float n  = params[(size_t)((b0 + bi) * 50 + 48 + which) * NFR + f];
        float db = fmaf(n, 60.0f, -60.0f);
        ((float*)&sh_gain[which])[bi] = exp10f(db * 0.05f);
    }
    __syncthreads();

    // ---------------- load audio (packed, stays in registers) ----------------
    const ull ingp  = sh_gain[0];
    const ull outgp = sh_gain[1];
    ull x[SPT];
    {
        const size_t off = (size_t)f * FRAME + t * SPT;
        const float4* a0 = (const float4*)(audio + (size_t)b0 * 49152 + off);
        const float4* a1 = (const float4*)(audio + (size_t)(b0 + 1) * 49152 + off);
        #pragma unroll
        for (int j = 0; j < 2; j++) {
            float4 u = a0[j], v = a1[j];
            x[4 * j + 0] = mul2(pack2(u.x, v.x), ingp);
            x[4 * j + 1] = mul2(pack2(u.y, v.y), ingp);
            x[4 * j + 2] = mul2(pack2(u.z, v.z), ingp);
            x[4 * j + 3] = mul2(pack2(u.w, v.w), ingp);
        }
    }

    // ---------------- filter cascade ----------------
    for (int i = 0; i < NB; i++) {
        const int buf = i & 1;
        const ull a1p = cf[i][0], a2p = cf[i][1], a3p = cf[i][2];
        const ull m0p = cf[i][3], m1p = cf[i][4], m2p = cf[i][5];

        // zero-state sim over 8 samples -> segment offset (c1,c2)
        ull c1 = 0ull, c2 = 0ull;
        #pragma unroll
        for (int j = 0; j < SPT; j++) {
            ull v3 = fma2(c2, NEG1_2, x[j]);           // x - c2 (exact)
            ull v1 = fma2(a1p, c1, mul2(a2p, v3));
            ull v2 = fma2(a2p, v1, fma2(a3p, v3, c2));
            c1 = fma2(TWO2, v1, neg2(c1));
            c2 = fma2(TWO2, v2, neg2(c2));
        }

        // state transition A, then A^8
        M2p M;
        M.a = fma2(TWO2, a1p, NEG1_2);                 // 2a1 - 1
        M.b = mul2(NEGTWO2, a2p);                      // -2a2
        M.c = mul2(TWO2, mul2(a1p, a2p));              // 2a1a2
        M.d = fma2(NEGTWO2, fma2(a2p, a2p, a3p), ONE2);// 1 - 2(a2^2 + a3)
        M = msq(msq(msq(M)));                          // A^8

        // warp affine scan; build L = A^(8*lane) on the side
        M2p L; L.a = ONE2; L.b = 0ull; L.c = 0ull; L.d = ONE2;
        #pragma unroll
        for (int k = 0; k < 5; k++) {
            ull o1 = __shfl_up_sync(0xFFFFFFFFu, c1, 1 << k);
            ull o2 = __shfl_up_sync(0xFFFFFFFFu, c2, 1 << k);
            if (lane >= (1 << k)) {
                c1 = fma2(M.a, o1, fma2(M.b, o2, c1));
                c2 = fma2(M.c, o1, fma2(M.d, o2, c2));
            }
            if (lane & (1 << k)) L = mmul(M, L);
            M = msq(M);                                // after loop: A^256
        }

        // within-warp exclusive offset
        ull e1 = __shfl_up_sync(0xFFFFFFFFu, c1, 1);
        ull e2 = __shfl_up_sync(0xFFFFFFFFu, c2, 1);
        if (lane == 0) { e1 = 0ull; e2 = 0ull; }

        if (lane == 31) { shT[buf][w][0] = c1; shT[buf][w][1] = c2; }
        __syncthreads();

        // thread 0: obtain frame-in state, publish frame-out state ASAP
        if (t == 0) {
            ull si1 = 0ull, si2 = 0ull;
            if (f > 0) {
                const ull* p0 = &g_state[((size_t)b0 * NFR + (f - 1)) * NB + i];
                const ull* p1 = &g_state[((size_t)(b0 + 1) * NFR + (f - 1)) * NB + i];
                ull v0 = ld_relaxed_u64(p0);
                while (v0 == SVAL) { __nanosleep(32); v0 = ld_relaxed_u64(p0); }
                ull v1 = ld_relaxed_u64(p1);
                while (v1 == SVAL) { __nanosleep(32); v1 = ld_relaxed_u64(p1); }
                // per-batch word: (s2 << 32) | s1  ->  packed across batches
                si1 = (v0 & 0xFFFFFFFFull) | (v1 << 32);
                si2 = (v0 >> 32) | (v1 & 0xFFFFFFFF00000000ull);
            }
            if (f < NFR - 1) {
                ull S1 = si1, S2 = si2;
                #pragma unroll
                for (int j = 0; j < NW; j++) {
                    ull n1 = fma2(M.a, S1, fma2(M.b, S2, shT[buf][j][0]));
                    ull n2 = fma2(M.c, S1, fma2(M.d, S2, shT[buf][j][1]));
                    S1 = n1; S2 = n2;
                }
                ull w0 = (S1 & 0xFFFFFFFFull) | (S2 << 32);
                ull w1 = (S1 >> 32) | (S2 & 0xFFFFFFFF00000000ull);
                st_relaxed_u64(&g_state[((size_t)b0 * NFR + f) * NB + i], w0);
                st_relaxed_u64(&g_state[((size_t)(b0 + 1) * NFR + f) * NB + i], w1);
            }
            sh_sin[0] = si1; sh_sin[1] = si2;
        }
        __syncthreads();

        // warp-in state: chain through earlier warps' totals (warp-uniform)
        ull S1 = sh_sin[0], S2 = sh_sin[1];
        #pragma unroll
        for (int j = 0; j < NW - 1; j++) {
            if (j < w) {
                ull n1 = fma2(M.a, S1, fma2(M.b, S2, shT[buf][j][0]));
                ull n2 = fma2(M.c, S1, fma2(M.d, S2, shT[buf][j][1]));
                S1 = n1; S2 = n2;
            }
        }

        // thread-in state = L * S_w + e
        ull s1 = fma2(L.a, S1, fma2(L.b, S2, e1));
        ull s2 = fma2(L.c, S1, fma2(L.d, S2, e2));

        // exact re-simulation producing outputs (reference arithmetic)
        #pragma unroll
        for (int j = 0; j < SPT; j++) {
            ull xn = x[j];
            ull v3 = fma2(s2, NEG1_2, xn);
            ull v1 = fma2(a1p, s1, mul2(a2p, v3));
            ull v2 = fma2(a2p, v1, fma2(a3p, v3, s2));
            x[j] = fma2(m0p, xn, fma2(m1p, v1, mul2(m2p, v2)));
            s1 = fma2(TWO2, v1, neg2(s1));
            s2 = fma2(TWO2, v2, neg2(s2));
        }
    }

    // ---------------- store output ----------------
    {
        const size_t off = (size_t)f * FRAME + t * SPT;
        float4* o0 = (float4*)(out + (size_t)b0 * 49152 + off);
        float4* o1 = (float4*)(out + (size_t)(b0 + 1) * 49152 + off);
        #pragma unroll
        for (int j = 0; j < 2; j++) {
            ull y0 = mul2(x[4 * j + 0], outgp);
            ull y1 = mul2(x[4 * j + 1], outgp);
            ull y2 = mul2(x[4 * j + 2], outgp);
            ull y3 = mul2(x[4 * j + 3], outgp);
            float4 u, v;
            u.x = lo2(y0); u.y = lo2(y1); u.z = lo2(y2); u.w = lo2(y3);
            v.x = hi2(y0); v.y = hi2(y1); v.z = hi2(y2); v.w = hi2(y3);
            o0[j] = u;
            o1[j] = v;
        }
    }
}

extern "C" void kernel_launch(void* const* d_in, const int* in_sizes, int n_in,
                              void* d_out, int out_size) {
    const float* audio;
    const float* params;
    if (in_sizes[0] > in_sizes[1]) { audio = (const float*)d_in[0]; params = (const float*)d_in[1]; }
    else                           { audio = (const float*)d_in[1]; params = (const float*)d_in[0]; }
    float* out = (float*)d_out;

    init_state_kernel<<<(BATCH * NFR * NB + 255) / 256, 256>>>();
    eq_kernel<<<NFR * NPAIR, TPB>>>(audio, params, out);
}

// round 9
// speedup vs baseline: 1.6773x; 1.6773x over previous
#include <cuda_runtime.h>
#include <cstdint>

// ---------------------------------------------------------------------------
// DifferentiableBiquadChain: 16 cascaded SVF biquads, per-frame coefficients.
//
// Block = (batch b, frame f), 128 threads x 16 samples each.
// Per filter: prefetch predecessor frame state (relaxed 64-bit load, hidden
// under compute) -> zero-state segment sim -> warp affine scan (constant-A
// per frame, matrix powers by repeated squaring) -> ONE barrier -> per-warp
// chain from the prefetched state -> publish (thread 0) -> exact re-sim with
// reference arithmetic. Audio stays in registers across all 16 stages.
// ---------------------------------------------------------------------------

#define NB      16
#define FRAME   2048
#define NFR     24
#define BATCH   32
#define TPB     128
#define SPT     16
#define NW      4
#define SVAL    0xFFFFFFFFFFFFFFFFull

typedef unsigned long long ull;

__device__ ull g_state[BATCH * NFR * NB];

__global__ void init_state_kernel() {
    int i = blockIdx.x * blockDim.x + threadIdx.x;
    if (i < BATCH * NFR * NB) g_state[i] = SVAL;
}

struct M2 { float a, b, c, d; }; // [[a,b],[c,d]]

__device__ __forceinline__ M2 msq(M2 m) {
    M2 r;
    float apd = m.a + m.d;
    float bc  = m.b * m.c;
    r.a = fmaf(m.a, m.a, bc);
    r.b = m.b * apd;
    r.c = m.c * apd;
    r.d = fmaf(m.d, m.d, bc);
    return r;
}

__device__ __forceinline__ M2 mmul(M2 p, M2 q) {
    M2 r;
    r.a = fmaf(p.a, q.a, p.b * q.c);
    r.b = fmaf(p.a, q.b, p.b * q.d);
    r.c = fmaf(p.c, q.a, p.d * q.c);
    r.d = fmaf(p.c, q.b, p.d * q.d);
    return r;
}

__device__ __forceinline__ ull ld_relaxed_u64(const ull* p) {
    ull v;
    asm volatile("ld.relaxed.gpu.global.u64 %0, [%1];" : "=l"(v) : "l"(p) : "memory");
    return v;
}
__device__ __forceinline__ void st_relaxed_u64(ull* p, ull v) {
    asm volatile("st.relaxed.gpu.global.u64 [%0], %1;" : : "l"(p), "l"(v) : "memory");
}

__global__ __launch_bounds__(TPB, 6)
void eq_kernel(const float* __restrict__ audio,
               const float* __restrict__ params,
               float* __restrict__ out)
{
    const int blk  = blockIdx.x;
    const int f    = blk >> 5;   // frame (f-major: predecessors have lower blockIdx)
    const int b    = blk & 31;   // batch
    const int t    = threadIdx.x;
    const int lane = t & 31;
    const int w    = t >> 5;

    __shared__ float cf[NB][6];       // a1 a2 a3 m0 m1 m2
    __shared__ float sh_gain[2];      // in_g, out_g
    __shared__ float shTa[2][NW];     // warp totals c1 (double-buffered)
    __shared__ float shTb[2][NW];     // warp totals c2

    // ---------------- coefficients (threads 0..17) ----------------
    if (t < NB) {
        const float* pb = params + (size_t)(b * 50) * NFR + f;
        float fn = pb[(t * 3 + 0) * NFR];
        float gn = pb[(t * 3 + 1) * NFR];
        float qn = pb[(t * 3 + 2) * NFR];

        // Q = exp(ln0.5 + qn*(ln16 - ln0.5)), clip [0.1, 100]
        float Q = expf(fmaf(qn, 3.4657359f, -0.6931472f));
        Q = fminf(fmaxf(Q, 0.1f), 100.0f);

        float gain = fmaf(gn, 48.0f, -24.0f);
        float A  = exp10f(gain * 0.025f);   // 10^(gain/40)
        float sA = sqrtf(A);

        float lnlo, lnhi;
        if      (t == 0)            { lnlo = 2.9957323f; lnhi = 6.2146081f; } // HPF 20..500
        else if (t == 15)           { lnlo = 8.5171932f; lnhi = 9.9034876f; } // LPF 5k..20k
        else if (t == 1 || t == 14) { lnlo = 3.9120230f; lnhi = 9.6803184f; } // shelf 50..16k
        else                        { lnlo = 4.6051702f; lnhi = 9.6158055f; } // peak 100..15k
        float fc = expf(fmaf(fn, (lnhi - lnlo), lnlo));
        float g  = tanf(fc * 3.27249235e-5f);           // tan(pi*fc/96000)
        g = fminf(fmaxf(g, 1e-6f), 100.0f);

        float a1, a2, a3, m0, m1, m2;
        if (t == 0) {            // highpass
            float k = 1.0f / Q;
            a1 = 1.0f / (1.0f + g * (g + k)); a2 = g * a1; a3 = g * a2;
            m0 = 1.0f; m1 = -k; m2 = -1.0f;
        } else if (t == 15) {    // lowpass
            float k = 1.0f / Q;
            a1 = 1.0f / (1.0f + g * (g + k)); a2 = g * a1; a3 = g * a2;
            m0 = 0.0f; m1 = 0.0f; m2 = 1.0f;
        } else if (t == 1) {     // lowshelf
            float k = 1.0f / Q;
            float gs = (gain >= 0.0f) ? (g / sA) : (g * sA);
            a1 = 1.0f / (1.0f + gs * (gs + k)); a2 = gs * a1; a3 = gs * a2;
            m0 = 1.0f; m1 = k * (A - 1.0f); m2 = A * A - 1.0f;
        } else if (t == 14) {    // highshelf
            float k = 1.0f / Q;
            float gs = (gain >= 0.0f) ? (g * sA) : (g / sA);
            a1 = 1.0f / (1.0f + gs * (gs + k)); a2 = gs * a1; a3 = gs * a2;
            m0 = A * A; m1 = k * (1.0f - A) * A; m2 = 1.0f - A * A;
        } else {                 // peak
            float k = (gain >= 0.0f) ? (1.0f / (Q * A)) : (A / Q);
            a1 = 1.0f / (1.0f + g * (g + k)); a2 = g * a1; a3 = g * a2;
            m0 = 1.0f; m1 = k * (A * A - 1.0f); m2 = 0.0f;
        }
        cf[t][0] = a1; cf[t][1] = a2; cf[t][2] = a3;
        cf[t][3] = m0; cf[t][4] = m1; cf[t][5] = m2;
    } else if (t == 16 || t == 17) {
        float n  = params[(size_t)(b * 50 + 48 + (t - 16)) * NFR + f];
        float db = fmaf(n, 60.0f, -60.0f);
        sh_gain[t - 16] = exp10f(db * 0.05f);  // 10^(db/20)
    }
    __syncthreads();

    // ---------------- load audio (x stays in registers) ----------------
    const float ing  = sh_gain[0];
    const float outg = sh_gain[1];
    float x[SPT];
    {
        const float4* ap = (const float4*)(audio + (size_t)b * 49152 + f * FRAME + t * SPT);
        #pragma unroll
        for (int j = 0; j < 4; j++) {
            float4 v = ap[j];
            x[4 * j + 0] = v.x * ing;
            x[4 * j + 1] = v.y * ing;
            x[4 * j + 2] = v.z * ing;
            x[4 * j + 3] = v.w * ing;
        }
    }

    const ull* src_base = (f > 0) ? &g_state[((size_t)b * NFR + (f - 1)) * NB] : nullptr;
    ull* dst_base = (f < NFR - 1) ? &g_state[((size_t)b * NFR + f) * NB] : nullptr;

    // ---------------- filter cascade ----------------
    for (int i = 0; i < NB; i++) {
        const int buf = i & 1;
        const float a1 = cf[i][0], a2 = cf[i][1], a3 = cf[i][2];
        const float m0 = cf[i][3], m1 = cf[i][4], m2 = cf[i][5];

        // prefetch predecessor frame state (same address for all threads ->
        // broadcast; latency hidden under zero-sim + scan below)
        ull v = 0ull;
        if (f > 0) v = ld_relaxed_u64(src_base + i);

        // zero-state sim over this thread's 16 samples -> segment offset (c1,c2)
        float c1 = 0.0f, c2 = 0.0f;
        #pragma unroll
        for (int j = 0; j < SPT; j++) {
            float v3 = x[j] - c2;
            float v1 = fmaf(a1, c1, a2 * v3);
            float v2 = fmaf(a2, v1, fmaf(a3, v3, c2));
            c1 = fmaf(2.0f, v1, -c1);
            c2 = fmaf(2.0f, v2, -c2);
        }

        // state transition A, then A^16
        M2 M;
        M.a = fmaf(2.0f, a1, -1.0f);
        M.b = -2.0f * a2;
        M.c = 2.0f * a1 * a2;
        M.d = 1.0f - 2.0f * fmaf(a2, a2, a3);
        M = msq(msq(msq(msq(M))));  // A^16

        // warp affine scan; simultaneously build L = A^(16*lane)
        M2 L; L.a = 1.0f; L.b = 0.0f; L.c = 0.0f; L.d = 1.0f;
        #pragma unroll
        for (int k = 0; k < 5; k++) {
            float o1 = __shfl_up_sync(0xFFFFFFFFu, c1, 1 << k);
            float o2 = __shfl_up_sync(0xFFFFFFFFu, c2, 1 << k);
            if (lane >= (1 << k)) {
                c1 = fmaf(M.a, o1, fmaf(M.b, o2, c1));
                c2 = fmaf(M.c, o1, fmaf(M.d, o2, c2));
            }
            if (lane & (1 << k)) L = mmul(M, L);
            M = msq(M);             // after loop: M = A^512
        }

        // within-warp exclusive offset
        float e1 = __shfl_up_sync(0xFFFFFFFFu, c1, 1);
        float e2 = __shfl_up_sync(0xFFFFFFFFu, c2, 1);
        if (lane == 0) { e1 = 0.0f; e2 = 0.0f; }

        if (lane == 31) { shTa[buf][w] = c1; shTb[buf][w] = c2; }
        __syncthreads();

        // finish the spin if the prefetch raced the predecessor
        if (f > 0 && v == SVAL) {
            do { __nanosleep(32); v = ld_relaxed_u64(src_base + i); } while (v == SVAL);
        }
        const float si1 = __uint_as_float((unsigned)(v & 0xFFFFFFFFu));
        const float si2 = __uint_as_float((unsigned)(v >> 32));

        // thread 0 (warp 0 has no chain work): compute frame-out, publish ASAP
        if (t == 0 && dst_base != nullptr) {
            float S1 = si1, S2 = si2;
            #pragma unroll
            for (int j = 0; j < NW; j++) {
                float n1 = fmaf(M.a, S1, fmaf(M.b, S2, shTa[buf][j]));
                float n2 = fmaf(M.c, S1, fmaf(M.d, S2, shTb[buf][j]));
                S1 = n1; S2 = n2;
            }
            ull pv = ((ull)__float_as_uint(S2) << 32) | (ull)__float_as_uint(S1);
            st_relaxed_u64(dst_base + i, pv);
        }

        // warp-in state: chain through earlier warps' totals (warp-uniform)
        float S1 = si1, S2 = si2;
        #pragma unroll
        for (int j = 0; j < NW - 1; j++) {
            if (j < w) {
                float n1 = fmaf(M.a, S1, fmaf(M.b, S2, shTa[buf][j]));
                float n2 = fmaf(M.c, S1, fmaf(M.d, S2, shTb[buf][j]));
                S1 = n1; S2 = n2;
            }
        }

        // thread-in state = L * S_w + e
        float s1 = fmaf(L.a, S1, fmaf(L.b, S2, e1));
        float s2 = fmaf(L.c, S1, fmaf(L.d, S2, e2));

        // exact re-simulation producing outputs (reference arithmetic)
        #pragma unroll
        for (int j = 0; j < SPT; j++) {
            float xn = x[j];
            float v3 = xn - s2;
            float v1 = fmaf(a1, s1, a2 * v3);
            float v2 = fmaf(a2, v1, fmaf(a3, v3, s2));
            x[j] = fmaf(m0, xn, fmaf(m1, v1, m2 * v2));
            s1 = fmaf(2.0f, v1, -s1);
            s2 = fmaf(2.0f, v2, -s2);
        }
    }

    // ---------------- store output ----------------
    {
        float4* op = (float4*)(out + (size_t)b * 49152 + f * FRAME + t * SPT);
        #pragma unroll
        for (int j = 0; j < 4; j++) {
            float4 v;
            v.x = x[4 * j + 0] * outg;
            v.y = x[4 * j + 1] * outg;
            v.z = x[4 * j + 2] * outg;
            v.w = x[4 * j + 3] * outg;
            op[j] = v;
        }
    }
}

extern "C" void kernel_launch(void* const* d_in, const int* in_sizes, int n_in,
                              void* d_out, int out_size) {
    const float* audio;
    const float* params;
    if (in_sizes[0] > in_sizes[1]) { audio = (const float*)d_in[0]; params = (const float*)d_in[1]; }
    else                           { audio = (const float*)d_in[1]; params = (const float*)d_in[0]; }
    float* out = (float*)d_out;

    init_state_kernel<<<(BATCH * NFR * NB + 255) / 256, 256>>>();
    eq_kernel<<<BATCH * NFR, TPB>>>(audio, params, out);
}